// round 16
// baseline (speedup 1.0000x reference)
#include <cuda_runtime.h>
#include <cuda_bf16.h>
#include <cstdint>

// Problem constants
#define BB    64
#define TT    256
#define KK    256      // INPUT_SIZE
#define LBL   51       // L
#define NN    2601     // L*L
#define NPAD  2688     // 21 * 128
#define MM    16384    // B*T
#define CSZ   16       // scan chunk size
#define NCH   16       // chunks per batch
#define MSTR  3264     // 51 * 64 fp32 chunk-matrix storage
#define XB    3672     // bf16 elems per (b,t) X-block: 51 rows * 72 cols (144B rows)
#define XCHUNKS 459    // 7344 B / 16

// ---------------------------------------------------------------------------
// Device globals (no allocations allowed)
// ---------------------------------------------------------------------------
__device__ __align__(256) __nv_bfloat16 g_Abf[MM * KK];
__device__ __align__(256) __nv_bfloat16 g_Wpb[NPAD * KK];
__device__ __align__(256) float         g_bp[NPAD];
__device__ __align__(256) __nv_bfloat16 g_Xp[(size_t)MM * XB + 64]; // padded X blocks (~120MB)
__device__ __align__(256) float         g_M[(size_t)BB * NCH * MSTR];
__device__ __align__(256) float         g_lsc[BB * NCH];

// ---------------------------------------------------------------------------
// Helpers
// ---------------------------------------------------------------------------
__device__ __forceinline__ uint32_t smem_u32(const void* p) {
    uint32_t a;
    asm("{ .reg .u64 t; cvta.to.shared.u64 t, %1; cvt.u32.u64 %0, t; }" : "=r"(a) : "l"(p));
    return a;
}
__device__ __forceinline__ void cp_async16(uint32_t smem, const void* g) {
    asm volatile("cp.async.cg.shared.global [%0], [%1], 16;\n" :: "r"(smem), "l"(g));
}
#define CP_COMMIT() asm volatile("cp.async.commit_group;\n" ::: "memory")
#define CP_WAIT(n)  asm volatile("cp.async.wait_group %0;\n" :: "n"(n) : "memory")

#define LDSM4(r0, r1, r2, r3, addr) \
    asm volatile("ldmatrix.sync.aligned.m8n8.x4.shared.b16 {%0,%1,%2,%3}, [%4];\n" \
                 : "=r"(r0), "=r"(r1), "=r"(r2), "=r"(r3) : "r"(addr))

#define LDSM4_T(r0, r1, r2, r3, addr) \
    asm volatile("ldmatrix.sync.aligned.m8n8.x4.trans.shared.b16 {%0,%1,%2,%3}, [%4];\n" \
                 : "=r"(r0), "=r"(r1), "=r"(r2), "=r"(r3) : "r"(addr))

#define MMA16816(c, a, b) \
    asm volatile("mma.sync.aligned.m16n8k16.row.col.f32.bf16.bf16.f32 " \
                 "{%0,%1,%2,%3}, {%4,%5,%6,%7}, {%8,%9}, {%0,%1,%2,%3};\n" \
                 : "+f"((c)[0]), "+f"((c)[1]), "+f"((c)[2]), "+f"((c)[3]) \
                 : "r"((a)[0]), "r"((a)[1]), "r"((a)[2]), "r"((a)[3]), \
                   "r"((b)[0]), "r"((b)[1]))

// ---------------------------------------------------------------------------
// Fused prep kernel (unchanged)
// ---------------------------------------------------------------------------
#define PREP_A_BLOCKS 512
#define PREP_W_BLOCKS 336

__global__ __launch_bounds__(256, 1) void prep_kernel(
        const float* __restrict__ A,
        const float* __restrict__ sW, const float* __restrict__ sb,
        const float* __restrict__ tW, const float* __restrict__ tb) {
    if (blockIdx.x < PREP_A_BLOCKS) {
        const size_t base = (size_t)blockIdx.x * 2048 + threadIdx.x;
        const float4* A4 = (const float4*)A;
        float4 v[8];
#pragma unroll
        for (int h = 0; h < 8; h++) v[h] = A4[base + h * 256];
#pragma unroll
        for (int h = 0; h < 8; h++) {
            __nv_bfloat162 p0 = __floats2bfloat162_rn(v[h].x, v[h].y);
            __nv_bfloat162 p1 = __floats2bfloat162_rn(v[h].z, v[h].w);
            uint2 o;
            o.x = *(uint32_t*)&p0;
            o.y = *(uint32_t*)&p1;
            *(uint2*)&g_Abf[(base + h * 256) * 4] = o;
        }
        return;
    }
    const int idx = (blockIdx.x - PREP_A_BLOCKS) * 256 + threadIdx.x;
    const int kb  = idx / NPAD;
    const int n   = idx - kb * NPAD;
    if (n < NN) {
        const int col = n % LBL;
        if (kb == 0) g_bp[n] = tb[n] + sb[col];
        float v[8], w[8];
#pragma unroll
        for (int i = 0; i < 8; i++)
            v[i] = tW[(size_t)(kb * 8 + i) * NN + n];
#pragma unroll
        for (int i = 0; i < 8; i++)
            w[i] = sW[(kb * 8 + i) * LBL + col];
        __nv_bfloat162 p[4];
#pragma unroll
        for (int i = 0; i < 4; i++)
            p[i] = __floats2bfloat162_rn(v[2 * i] + w[2 * i], v[2 * i + 1] + w[2 * i + 1]);
        *(uint4*)&g_Wpb[n * KK + kb * 8] = *(uint4*)p;
    } else {
        if (kb == 0) g_bp[n] = 0.f;
        uint4 z = {0, 0, 0, 0};
        *(uint4*)&g_Wpb[n * KK + kb * 8] = z;
    }
}

// ---------------------------------------------------------------------------
// mma.sync GEMM + exp epilogue. Mainloop unchanged; copy-out writes padded
// X-blocks: g_Xp[(m)*XB + (n/51)*72 + n%51], guarded n < NN.
// ---------------------------------------------------------------------------
#define STG_ELEMS 136

__global__ __launch_bounds__(256, 2) void gemm_exp_kernel(const float* __restrict__ mask) {
    __shared__ __align__(128) char sm[49152];

    const int tid = threadIdx.x;
    const int l   = tid & 31;
    const int wid = tid >> 5;
    const int wm  = wid >> 2;
    const int wn  = wid & 3;
    const int m0  = blockIdx.y * 128;
    const int n0  = blockIdx.x * 128;

    const uint32_t smBase = smem_u32(sm);

    const int a_r = (l & 7) + 8 * ((l >> 3) & 1);
    const int a_s = (l >> 4);
    uint32_t a_off[4][2];
#pragma unroll
    for (int i = 0; i < 4; i++)
#pragma unroll
        for (int ks16 = 0; ks16 < 2; ks16++) {
            int r = wm * 64 + 16 * i + a_r;
            int seg = ks16 * 2 + a_s;
            a_off[i][ks16] = r * 64 + ((seg ^ (r & 3)) << 4);
        }
    const int b_r = (l & 7) + 8 * ((l >> 4) & 1);
    const int b_s = (l >> 3) & 1;
    uint32_t b_off[2][2];
#pragma unroll
    for (int jj = 0; jj < 2; jj++)
#pragma unroll
        for (int ks16 = 0; ks16 < 2; ks16++) {
            int r = wn * 32 + 16 * jj + b_r;
            int seg = ks16 * 2 + b_s;
            b_off[jj][ks16] = r * 64 + ((seg ^ (r & 3)) << 4);
        }

    const int c0r = tid >> 2, c0s = tid & 3;
    const int c1r = (tid + 256) >> 2, c1s = tid & 3;
    const uint32_t so0 = c0r * 64 + ((c0s ^ (c0r & 3)) << 4);
    const uint32_t so1 = c1r * 64 + ((c1s ^ (c1r & 3)) << 4);

#define LOAD_STAGE(s, ks) do {                                                        \
        uint32_t bA = smBase + (s) * 16384;                                           \
        uint32_t bW = bA + 8192;                                                      \
        cp_async16(bA + so0, g_Abf + (size_t)(m0 + c0r) * KK + (ks) * 32 + c0s * 8);  \
        cp_async16(bA + so1, g_Abf + (size_t)(m0 + c1r) * KK + (ks) * 32 + c1s * 8);  \
        cp_async16(bW + so0, g_Wpb + (size_t)(n0 + c0r) * KK + (ks) * 32 + c0s * 8);  \
        cp_async16(bW + so1, g_Wpb + (size_t)(n0 + c1r) * KK + (ks) * 32 + c1s * 8);  \
        CP_COMMIT();                                                                  \
    } while (0)

    float acc[4][4][4];
#pragma unroll
    for (int i = 0; i < 4; i++)
#pragma unroll
        for (int j = 0; j < 4; j++)
#pragma unroll
            for (int q = 0; q < 4; q++) acc[i][j][q] = 0.f;

    LOAD_STAGE(0, 0);
    LOAD_STAGE(1, 1);

#pragma unroll 1
    for (int ks = 0; ks < 8; ks++) {
        if (ks < 7) { CP_WAIT(1); } else { CP_WAIT(0); }
        __syncthreads();
        if (ks + 2 < 8) LOAD_STAGE((ks + 2) % 3, ks + 2);

        const uint32_t bA = smBase + (ks % 3) * 16384;
        const uint32_t bW = bA + 8192;

#pragma unroll
        for (int ks16 = 0; ks16 < 2; ks16++) {
            uint32_t a[4][4];
            uint32_t b[4][2];
#pragma unroll
            for (int i = 0; i < 4; i++)
                LDSM4(a[i][0], a[i][1], a[i][2], a[i][3], bA + a_off[i][ks16]);
#pragma unroll
            for (int jj = 0; jj < 2; jj++)
                LDSM4(b[2 * jj][0], b[2 * jj][1], b[2 * jj + 1][0], b[2 * jj + 1][1],
                      bW + b_off[jj][ks16]);
#pragma unroll
            for (int i = 0; i < 4; i++)
#pragma unroll
                for (int j = 0; j < 4; j++)
                    MMA16816(acc[i][j], a[i], b[j]);
        }
    }
    __syncthreads();

    __nv_bfloat16* stage = (__nv_bfloat16*)sm;
    const int qr = l >> 2, qc = l & 3;

    float bj0[4], bj1[4];
#pragma unroll
    for (int j = 0; j < 4; j++) {
        int n = n0 + wn * 32 + 8 * j + 2 * qc;
        bj0[j] = g_bp[n];
        bj1[j] = g_bp[n + 1];
    }

#pragma unroll
    for (int i = 0; i < 4; i++) {
        int mlo = wm * 64 + 16 * i + qr;
        float mk_lo = mask[m0 + mlo];
        float mk_hi = mask[m0 + mlo + 8];
#pragma unroll
        for (int j = 0; j < 4; j++) {
            int nl = wn * 32 + 8 * j + 2 * qc;
            float f00 = __expf(mk_lo * (acc[i][j][0] + bj0[j]));
            float f01 = __expf(mk_lo * (acc[i][j][1] + bj1[j]));
            float f10 = __expf(mk_hi * (acc[i][j][2] + bj0[j]));
            float f11 = __expf(mk_hi * (acc[i][j][3] + bj1[j]));
            *(__nv_bfloat162*)&stage[mlo * STG_ELEMS + nl]       = __floats2bfloat162_rn(f00, f01);
            *(__nv_bfloat162*)&stage[(mlo + 8) * STG_ELEMS + nl] = __floats2bfloat162_rn(f10, f11);
        }
    }
    __syncthreads();

    // Copy-out to padded X blocks: element (m, n) -> block m, row n/51, col n%51
#pragma unroll
    for (int h = 0; h < 8; h++) {
        int cc  = tid + h * 256;
        int row = cc >> 4;
        int seg = cc & 15;
        uint4 v = *(const uint4*)&stage[row * STG_ELEMS + seg * 8];
        const __nv_bfloat16* vv = (const __nv_bfloat16*)&v;
        size_t base = (size_t)(m0 + row) * XB;
        int nb = n0 + seg * 8;
#pragma unroll
        for (int e = 0; e < 8; e++) {
            int n = nb + e;
            if (n < NN) {
                int i = n / 51;
                g_Xp[base + i * 72 + (n - i * 51)] = vv[e];
            }
        }
    }
}

// ---------------------------------------------------------------------------
// S1: chunk transfer-matrix products, repack-free.
// B-fragments via ldmatrix.x4.trans directly on padded raw X blocks (144B rows,
// conflict-free). Producer warps 4-7: cp.async + per-row pad zeroing.
// Consumer warps 0-3: P <- max-rescale(P x X_t) via mma.sync.
// ---------------------------------------------------------------------------
#define TOFF(r, c) ((r) * 128 + ((((c) >> 3) ^ ((r) & 7)) << 4) + ((c) & 7) * 2)

__global__ __launch_bounds__(256) void s1_kernel(const float* __restrict__ mask) {
    const int c   = blockIdx.x;
    const int b   = blockIdx.y;
    const int tid = threadIdx.x;
    const int l   = tid & 31;
    const int wid = tid >> 5;

    const int t_first = (c == 0) ? 1 : c * CSZ;
    const int R = c * CSZ + CSZ - t_first;   // 15 (c==0) or 16

    __shared__ __align__(16) __nv_bfloat16 raw[4 * XB + 1024];  // ring + zero guard
    __shared__ __align__(16) __nv_bfloat16 P[64 * 64];
    __shared__ float sMax[4];
    __shared__ float s_m[CSZ];

    const __nv_bfloat16* Xc0 = g_Xp + (size_t)(b * TT + t_first) * XB;
    char* Pb = (char*)P;

    if (tid < R) s_m[tid] = mask[b * TT + t_first + tid];
    {
        uint4 z = {0, 0, 0, 0};
        for (int i = tid; i < 512; i += 256) ((uint4*)P)[i] = z;          // zero P
        for (int i = tid; i < 128; i += 256) ((uint4*)(raw + 4 * XB))[i] = z; // zero guard
    }

    // Producer prologue: issue rows 0..3 (clamped), ensure rows 0..2 arrived
    if (tid >= 128) {
        const int c0 = tid - 128;
        for (int r = 0; r < 4; r++) {
            int rr = (r < R) ? r : (R - 1);
            const char* src = (const char*)(Xc0 + (size_t)rr * XB);
            uint32_t dst = smem_u32(raw + r * XB);
            for (int ch = c0; ch < XCHUNKS; ch += 128) cp_async16(dst + ch * 16, src + ch * 16);
            CP_COMMIT();
        }
        CP_WAIT(1);   // rows 0,1,2 arrived
        if (c0 < LBL) {  // zero col-pads of row-1 block (bytes 102..143 per row)
            char* rowp = (char*)(raw + 1 * XB) + c0 * 144;
            uint2 z8 = {0, 0};
            *(uint16_t*)(rowp + 102) = 0;
            *(uint2*)(rowp + 104) = z8; *(uint2*)(rowp + 112) = z8;
            *(uint2*)(rowp + 120) = z8; *(uint2*)(rowp + 128) = z8;
            *(uint2*)(rowp + 136) = z8;
        }
    }
    __syncthreads();  // rows 0,1,2 + row-1 pads + P-zero + s_m visible

    // P init = X_{t_first} (or identity if masked). Only cols < 51 copied; pads stay 0.
    if (tid < 128) {
        if (s_m[0] != 0.f) {
            for (int e = tid; e < LBL * LBL; e += 128) {
                int i = e / LBL, j = e - i * LBL;
                *(__nv_bfloat16*)(Pb + TOFF(i, j)) = raw[i * 72 + j];
            }
        } else if (tid < LBL) {
            *(__nv_bfloat16*)(Pb + TOFF(tid, tid)) = __float2bfloat16(1.f);
        }
    }

    // Consumer fragment offsets
    const int mh = (wid >> 1) & 1, nh = wid & 1;
    const int a_r = l & 15, a_s = l >> 4;
    uint32_t a_off[2][4];
#pragma unroll
    for (int i = 0; i < 2; i++)
#pragma unroll
        for (int kk = 0; kk < 4; kk++) {
            int r = mh * 32 + 16 * i + a_r;
            int seg = 2 * kk + a_s;
            a_off[i][kk] = r * 128 + ((seg ^ (r & 7)) << 4);
        }
    // trans B offsets: lane -> X row 16kk + 8*((l>>3)&1) + (l&7),
    //                  col-byte (nh*32 + 16*jj + 8*(l>>4)) * 2
    const int bk = 8 * ((l >> 3) & 1) + (l & 7);
    const int bnb = (nh * 32 + 8 * (l >> 4)) * 2;
    uint32_t bt_off[2][4];
#pragma unroll
    for (int jj = 0; jj < 2; jj++)
#pragma unroll
        for (int kk = 0; kk < 4; kk++)
            bt_off[jj][kk] = (uint32_t)((16 * kk + bk) * 144 + bnb + 32 * jj);
    const uint32_t smP = smem_u32(P);
    const uint32_t smRaw0 = smem_u32(raw);

    float lsc = 0.f;

#pragma unroll 1
    for (int s = 1; s < R; s++) {
        __syncthreads();  // row s + pads + previous P visible; slot (s+3)&3 free

        if (tid >= 128) {
            // issue row s+3 (clamped), ensure row s+2 arrived, zero row s+1 pads
            int sf = s + 3; if (sf >= R) sf = R - 1;
            const char* src = (const char*)(Xc0 + (size_t)sf * XB);
            uint32_t dst = smem_u32(raw + ((s + 3) & 3) * XB);
            const int c0 = tid - 128;
            for (int ch = c0; ch < XCHUNKS; ch += 128) cp_async16(dst + ch * 16, src + ch * 16);
            CP_COMMIT();
            CP_WAIT(1);  // rows <= s+2 arrived
            if (s + 1 < R && c0 < LBL) {
                char* rowp = (char*)(raw + ((s + 1) & 3) * XB) + c0 * 144;
                uint2 z8 = {0, 0};
                *(uint16_t*)(rowp + 102) = 0;
                *(uint2*)(rowp + 104) = z8; *(uint2*)(rowp + 112) = z8;
                *(uint2*)(rowp + 120) = z8; *(uint2*)(rowp + 128) = z8;
                *(uint2*)(rowp + 136) = z8;
            }
        } else if (s_m[s] != 0.f) {
            const uint32_t smRaw = smRaw0 + ((s & 3) * XB) * 2;
            float cacc[2][4][4];
            float wmax = 0.f;
#pragma unroll
            for (int i = 0; i < 2; i++)
#pragma unroll
                for (int j = 0; j < 4; j++)
#pragma unroll
                    for (int q = 0; q < 4; q++) cacc[i][j][q] = 0.f;
#pragma unroll
            for (int kk = 0; kk < 4; kk++) {
                uint32_t a[2][4], bb[4][2];
#pragma unroll
                for (int i = 0; i < 2; i++)
                    LDSM4(a[i][0], a[i][1], a[i][2], a[i][3], smP + a_off[i][kk]);
#pragma unroll
                for (int jj = 0; jj < 2; jj++)
                    LDSM4_T(bb[2 * jj][0], bb[2 * jj][1], bb[2 * jj + 1][0], bb[2 * jj + 1][1],
                            smRaw + bt_off[jj][kk]);
#pragma unroll
                for (int i = 0; i < 2; i++)
#pragma unroll
                    for (int j = 0; j < 4; j++)
                        MMA16816(cacc[i][j], a[i], bb[j]);
            }
#pragma unroll
            for (int i = 0; i < 2; i++)
#pragma unroll
                for (int j = 0; j < 4; j++)
#pragma unroll
                    for (int q = 0; q < 4; q++) wmax = fmaxf(wmax, cacc[i][j][q]);
#pragma unroll
            for (int o = 16; o > 0; o >>= 1)
                wmax = fmaxf(wmax, __shfl_xor_sync(0xffffffffu, wmax, o));
            if (l == 0) sMax[wid] = wmax;
            asm volatile("bar.sync 1, 128;" ::: "memory");
            {
                float mx = fmaxf(fmaxf(sMax[0], sMax[1]), fmaxf(sMax[2], sMax[3]));
                float inv = __fdividef(1.f, mx);
                const int qr = l >> 2, qc = l & 3;
#pragma unroll
                for (int i = 0; i < 2; i++) {
                    int mr = mh * 32 + 16 * i + qr;
#pragma unroll
                    for (int j8 = 0; j8 < 4; j8++) {
                        int nc = nh * 32 + 8 * j8 + 2 * qc;
                        *(__nv_bfloat162*)(Pb + TOFF(mr, nc)) =
                            __floats2bfloat162_rn(cacc[i][j8][0] * inv, cacc[i][j8][1] * inv);
                        *(__nv_bfloat162*)(Pb + TOFF(mr + 8, nc)) =
                            __floats2bfloat162_rn(cacc[i][j8][2] * inv, cacc[i][j8][3] * inv);
                    }
                }
                if (tid == 0) lsc += __logf(mx);
            }
        }
    }
    __syncthreads();

    float* Mo = g_M + (size_t)(b * NCH + c) * MSTR;
    for (int e = tid; e < MSTR; e += 256) {
        int m = e >> 6, j = e & 63;
        Mo[e] = __bfloat162float(*(const __nv_bfloat16*)(Pb + TOFF(m, j)));
    }
    if (tid == 0) g_lsc[b * NCH + c] = lsc;
}

// ---------------------------------------------------------------------------
// S2: per-batch combine, 3-buffer lead-2 prefetch (indices adapted to g_Xp).
// ---------------------------------------------------------------------------
__global__ __launch_bounds__(256) void s2_kernel(const int* __restrict__ target,
                                                 float* __restrict__ out) {
    const int b   = blockIdx.x;
    const int tid = threadIdx.x;
    const int l   = tid & 31;
    const int wid = tid >> 5;
    const int j   = tid & 63;
    const int g   = tid >> 6;

    __shared__ float v[64];
    __shared__ float red[256];
    __shared__ float wsum[8];
    __shared__ float sc[1];
    __shared__ float s_lsc[NCH];
    __shared__ int   s_tg[TT];
    __shared__ __align__(16) float Mb[3][MSTR];

    const __nv_bfloat16* Xb = g_Xp + (size_t)b * TT * XB;

    s_tg[tid] = target[b * TT + tid];
    if (tid < NCH) s_lsc[tid] = g_lsc[b * NCH + tid];

#pragma unroll
    for (int r = 0; r < 3; r++) {
        const char* src = (const char*)(g_M + (size_t)(b * NCH + r) * MSTR);
        uint32_t dst = smem_u32(Mb[r]);
        for (int ch = tid; ch < MSTR / 4; ch += 256) cp_async16(dst + ch * 16, src + ch * 16);
        CP_COMMIT();
    }
    __syncthreads();  // s_tg ready

    // target energy: thread tid == timestep t; X_t[prev, tg] at block offset prev*72+tg
    {
        int prev = (tid == 0) ? (LBL - 1) : s_tg[tid - 1];
        float e = __logf(__bfloat162float(Xb[(size_t)tid * XB + prev * 72 + s_tg[tid]]));
#pragma unroll
        for (int o = 16; o > 0; o >>= 1) e += __shfl_xor_sync(0xffffffffu, e, o);
        if (l == 0) wsum[wid] = e;
    }
    if (tid < 64)
        v[tid] = (tid < LBL) ? __bfloat162float(Xb[50 * 72 + tid]) : 0.f;  // t=0, row L-1

    float L = 0.f;

#pragma unroll 1
    for (int c = 0; c < NCH; c++) {
        CP_WAIT(2);
        __syncthreads();

        const float* M = Mb[c % 3];
        float sacc = 0.f;
#pragma unroll
        for (int it = 0; it < 13; it++) {
            int i = g + 4 * it;
            if (i < LBL) sacc += v[i] * M[i * 64 + j];
        }
        red[tid] = sacc;
        __syncthreads();

        if (c + 3 < NCH) {
            const char* src = (const char*)(g_M + (size_t)(b * NCH + c + 3) * MSTR);
            uint32_t dst = smem_u32(Mb[c % 3]);
            for (int ch = tid; ch < MSTR / 4; ch += 256) cp_async16(dst + ch * 16, src + ch * 16);
            CP_COMMIT();
        }

        if (g == 0) {
            float tot = red[j] + red[j + 64] + red[j + 128] + red[j + 192];
            red[j] = tot;
            if (j == 0) sc[0] = tot;
        }
        __syncthreads();
        if (g == 0) {
            float inv = __fdividef(1.f, sc[0]);
            v[j] = red[j] * inv;
            if (tid == 0) L += __logf(sc[0]) + s_lsc[c];
        }
    }
    __syncthreads();

    if (tid == 0) {
        float tg = 0.f;
#pragma unroll
        for (int w = 0; w < 8; w++) tg += wsum[w];
        float sm = 0.f;
        for (int jj = 0; jj < LBL; jj++) sm += v[jj];
        out[b] = L + __logf(sm) - tg;
    }
}

// ---------------------------------------------------------------------------
extern "C" void kernel_launch(void* const* d_in, const int* in_sizes, int n_in,
                              void* d_out, int out_size) {
    const float* input  = (const float*)d_in[0];
    const float* mask   = (const float*)d_in[1];
    const int*   target = (const int*)d_in[2];
    const float* sW     = (const float*)d_in[3];
    const float* sb     = (const float*)d_in[4];
    const float* tW     = (const float*)d_in[5];
    const float* tb     = (const float*)d_in[6];
    float* out = (float*)d_out;

    (void)in_sizes; (void)n_in; (void)out_size;

    prep_kernel<<<PREP_A_BLOCKS + PREP_W_BLOCKS, 256>>>(input, sW, sb, tW, tb);

    dim3 ggrid(NPAD / 128, MM / 128);  // (21, 128)
    gemm_exp_kernel<<<ggrid, 256>>>(mask);

    dim3 sgrid(NCH, BB);               // (16, 64)
    s1_kernel<<<sgrid, 256>>>(mask);

    s2_kernel<<<BB, 256>>>(target, out);
}

// round 17
// speedup vs baseline: 1.4960x; 1.4960x over previous
#include <cuda_runtime.h>
#include <cuda_bf16.h>
#include <cstdint>

// Problem constants
#define BB    64
#define TT    256
#define KK    256      // INPUT_SIZE
#define LBL   51       // L
#define NN    2601     // L*L
#define NN2   2652     // 51 * 52 (X padded to 52 cols per block-row)
#define NPAD  2688     // 21 * 128 (GEMM N grid; >= NN2)
#define ESTR  2688     // X row stride (bf16) = 5376 B
#define MM    16384    // B*T
#define CSZ   16
#define NCH   16
#define MSTR  3264     // 51*64 fp32 chunk matrices
#define SROWB 144      // s1 smem row stride (bytes)
#define SLOTB (51 * SROWB)   // 7344 B per ring slot
#define XCH8  663      // 51 rows * 13 8B-chunks per X block

// ---------------------------------------------------------------------------
// Device globals
// ---------------------------------------------------------------------------
__device__ __align__(256) __nv_bfloat16 g_Abf[MM * KK];
__device__ __align__(256) __nv_bfloat16 g_Wpb[NPAD * KK];
__device__ __align__(256) float         g_bp[NPAD];
__device__ __align__(256) __nv_bfloat16 g_X[(size_t)MM * ESTR];  // 52-col-padded X (~88MB)
__device__ __align__(256) float         g_M[(size_t)BB * NCH * MSTR];
__device__ __align__(256) float         g_lsc[BB * NCH];

// ---------------------------------------------------------------------------
// Helpers
// ---------------------------------------------------------------------------
__device__ __forceinline__ uint32_t smem_u32(const void* p) {
    uint32_t a;
    asm("{ .reg .u64 t; cvta.to.shared.u64 t, %1; cvt.u32.u64 %0, t; }" : "=r"(a) : "l"(p));
    return a;
}
__device__ __forceinline__ void cp_async16(uint32_t smem, const void* g) {
    asm volatile("cp.async.cg.shared.global [%0], [%1], 16;\n" :: "r"(smem), "l"(g));
}
__device__ __forceinline__ void cp_async8(uint32_t smem, const void* g) {
    asm volatile("cp.async.ca.shared.global [%0], [%1], 8;\n" :: "r"(smem), "l"(g));
}
#define CP_COMMIT() asm volatile("cp.async.commit_group;\n" ::: "memory")
#define CP_WAIT(n)  asm volatile("cp.async.wait_group %0;\n" :: "n"(n) : "memory")

#define LDSM4(r0, r1, r2, r3, addr) \
    asm volatile("ldmatrix.sync.aligned.m8n8.x4.shared.b16 {%0,%1,%2,%3}, [%4];\n" \
                 : "=r"(r0), "=r"(r1), "=r"(r2), "=r"(r3) : "r"(addr))

#define LDSM4_T(r0, r1, r2, r3, addr) \
    asm volatile("ldmatrix.sync.aligned.m8n8.x4.trans.shared.b16 {%0,%1,%2,%3}, [%4];\n" \
                 : "=r"(r0), "=r"(r1), "=r"(r2), "=r"(r3) : "r"(addr))

#define MMA16816(c, a, b) \
    asm volatile("mma.sync.aligned.m16n8k16.row.col.f32.bf16.bf16.f32 " \
                 "{%0,%1,%2,%3}, {%4,%5,%6,%7}, {%8,%9}, {%0,%1,%2,%3};\n" \
                 : "+f"((c)[0]), "+f"((c)[1]), "+f"((c)[2]), "+f"((c)[3]) \
                 : "r"((a)[0]), "r"((a)[1]), "r"((a)[2]), "r"((a)[3]), \
                   "r"((b)[0]), "r"((b)[1]))

// ---------------------------------------------------------------------------
// Fused prep: A->bf16 (MLP-8) and W-fold with 52-col padded mapping.
// Column n' = i*52 + j: valid (j<51, n'<NN2) -> n = i*51+j; else W=0, bias=-1e4.
// ---------------------------------------------------------------------------
#define PREP_A_BLOCKS 512
#define PREP_W_BLOCKS 336

__global__ __launch_bounds__(256, 1) void prep_kernel(
        const float* __restrict__ A,
        const float* __restrict__ sW, const float* __restrict__ sb,
        const float* __restrict__ tW, const float* __restrict__ tb) {
    if (blockIdx.x < PREP_A_BLOCKS) {
        const size_t base = (size_t)blockIdx.x * 2048 + threadIdx.x;
        const float4* A4 = (const float4*)A;
        float4 v[8];
#pragma unroll
        for (int h = 0; h < 8; h++) v[h] = A4[base + h * 256];
#pragma unroll
        for (int h = 0; h < 8; h++) {
            __nv_bfloat162 p0 = __floats2bfloat162_rn(v[h].x, v[h].y);
            __nv_bfloat162 p1 = __floats2bfloat162_rn(v[h].z, v[h].w);
            uint2 o;
            o.x = *(uint32_t*)&p0;
            o.y = *(uint32_t*)&p1;
            *(uint2*)&g_Abf[(base + h * 256) * 4] = o;
        }
        return;
    }
    const int idx = (blockIdx.x - PREP_A_BLOCKS) * 256 + threadIdx.x;
    const int kb  = idx / NPAD;
    const int np  = idx - kb * NPAD;   // padded column n'
    const int i   = np / 52;
    const int j   = np - i * 52;
    if (j < 51 && np < NN2) {
        const int n = i * LBL + j;
        if (kb == 0) g_bp[np] = tb[n] + sb[j];
        float v[8], w[8];
#pragma unroll
        for (int q = 0; q < 8; q++)
            v[q] = tW[(size_t)(kb * 8 + q) * NN + n];
#pragma unroll
        for (int q = 0; q < 8; q++)
            w[q] = sW[(kb * 8 + q) * LBL + j];
        __nv_bfloat162 p[4];
#pragma unroll
        for (int q = 0; q < 4; q++)
            p[q] = __floats2bfloat162_rn(v[2 * q] + w[2 * q], v[2 * q + 1] + w[2 * q + 1]);
        *(uint4*)&g_Wpb[np * KK + kb * 8] = *(uint4*)p;
    } else {
        if (kb == 0) g_bp[np] = -10000.f;  // exp(mask*(0-1e4)) = 0 for mask=1
        uint4 z = {0, 0, 0, 0};
        *(uint4*)&g_Wpb[np * KK + kb * 8] = z;
    }
}

// ---------------------------------------------------------------------------
// mma.sync GEMM + exp epilogue — byte-identical to the 186us round-15 version.
// ---------------------------------------------------------------------------
#define STG_ELEMS 136

__global__ __launch_bounds__(256, 2) void gemm_exp_kernel(const float* __restrict__ mask) {
    __shared__ __align__(128) char sm[49152];

    const int tid = threadIdx.x;
    const int l   = tid & 31;
    const int wid = tid >> 5;
    const int wm  = wid >> 2;
    const int wn  = wid & 3;
    const int m0  = blockIdx.y * 128;
    const int n0  = blockIdx.x * 128;

    const uint32_t smBase = smem_u32(sm);

    const int a_r = (l & 7) + 8 * ((l >> 3) & 1);
    const int a_s = (l >> 4);
    uint32_t a_off[4][2];
#pragma unroll
    for (int i = 0; i < 4; i++)
#pragma unroll
        for (int ks16 = 0; ks16 < 2; ks16++) {
            int r = wm * 64 + 16 * i + a_r;
            int seg = ks16 * 2 + a_s;
            a_off[i][ks16] = r * 64 + ((seg ^ (r & 3)) << 4);
        }
    const int b_r = (l & 7) + 8 * ((l >> 4) & 1);
    const int b_s = (l >> 3) & 1;
    uint32_t b_off[2][2];
#pragma unroll
    for (int jj = 0; jj < 2; jj++)
#pragma unroll
        for (int ks16 = 0; ks16 < 2; ks16++) {
            int r = wn * 32 + 16 * jj + b_r;
            int seg = ks16 * 2 + b_s;
            b_off[jj][ks16] = r * 64 + ((seg ^ (r & 3)) << 4);
        }

    const int c0r = tid >> 2, c0s = tid & 3;
    const int c1r = (tid + 256) >> 2, c1s = tid & 3;
    const uint32_t so0 = c0r * 64 + ((c0s ^ (c0r & 3)) << 4);
    const uint32_t so1 = c1r * 64 + ((c1s ^ (c1r & 3)) << 4);

#define LOAD_STAGE(s, ks) do {                                                        \
        uint32_t bA = smBase + (s) * 16384;                                           \
        uint32_t bW = bA + 8192;                                                      \
        cp_async16(bA + so0, g_Abf + (size_t)(m0 + c0r) * KK + (ks) * 32 + c0s * 8);  \
        cp_async16(bA + so1, g_Abf + (size_t)(m0 + c1r) * KK + (ks) * 32 + c1s * 8);  \
        cp_async16(bW + so0, g_Wpb + (size_t)(n0 + c0r) * KK + (ks) * 32 + c0s * 8);  \
        cp_async16(bW + so1, g_Wpb + (size_t)(n0 + c1r) * KK + (ks) * 32 + c1s * 8);  \
        CP_COMMIT();                                                                  \
    } while (0)

    float acc[4][4][4];
#pragma unroll
    for (int i = 0; i < 4; i++)
#pragma unroll
        for (int j = 0; j < 4; j++)
#pragma unroll
            for (int q = 0; q < 4; q++) acc[i][j][q] = 0.f;

    LOAD_STAGE(0, 0);
    LOAD_STAGE(1, 1);

#pragma unroll 1
    for (int ks = 0; ks < 8; ks++) {
        if (ks < 7) { CP_WAIT(1); } else { CP_WAIT(0); }
        __syncthreads();
        if (ks + 2 < 8) LOAD_STAGE((ks + 2) % 3, ks + 2);

        const uint32_t bA = smBase + (ks % 3) * 16384;
        const uint32_t bW = bA + 8192;

#pragma unroll
        for (int ks16 = 0; ks16 < 2; ks16++) {
            uint32_t a[4][4];
            uint32_t b[4][2];
#pragma unroll
            for (int i = 0; i < 4; i++)
                LDSM4(a[i][0], a[i][1], a[i][2], a[i][3], bA + a_off[i][ks16]);
#pragma unroll
            for (int jj = 0; jj < 2; jj++)
                LDSM4(b[2 * jj][0], b[2 * jj][1], b[2 * jj + 1][0], b[2 * jj + 1][1],
                      bW + b_off[jj][ks16]);
#pragma unroll
            for (int i = 0; i < 4; i++)
#pragma unroll
                for (int j = 0; j < 4; j++)
                    MMA16816(acc[i][j], a[i], b[j]);
        }
    }
    __syncthreads();

    __nv_bfloat16* stage = (__nv_bfloat16*)sm;
    const int qr = l >> 2, qc = l & 3;

    float bj0[4], bj1[4];
#pragma unroll
    for (int j = 0; j < 4; j++) {
        int n = n0 + wn * 32 + 8 * j + 2 * qc;
        bj0[j] = g_bp[n];
        bj1[j] = g_bp[n + 1];
    }

#pragma unroll
    for (int i = 0; i < 4; i++) {
        int mlo = wm * 64 + 16 * i + qr;
        float mk_lo = mask[m0 + mlo];
        float mk_hi = mask[m0 + mlo + 8];
#pragma unroll
        for (int j = 0; j < 4; j++) {
            int nl = wn * 32 + 8 * j + 2 * qc;
            float f00 = __expf(mk_lo * (acc[i][j][0] + bj0[j]));
            float f01 = __expf(mk_lo * (acc[i][j][1] + bj1[j]));
            float f10 = __expf(mk_hi * (acc[i][j][2] + bj0[j]));
            float f11 = __expf(mk_hi * (acc[i][j][3] + bj1[j]));
            *(__nv_bfloat162*)&stage[mlo * STG_ELEMS + nl]       = __floats2bfloat162_rn(f00, f01);
            *(__nv_bfloat162*)&stage[(mlo + 8) * STG_ELEMS + nl] = __floats2bfloat162_rn(f10, f11);
        }
    }
    __syncthreads();

#pragma unroll
    for (int h = 0; h < 8; h++) {
        int c = tid + h * 256;
        int row = c >> 4;
        int seg = c & 15;
        uint4 v = *(const uint4*)&stage[row * STG_ELEMS + seg * 8];
        *(uint4*)&g_X[(size_t)(m0 + row) * ESTR + n0 + seg * 8] = v;
    }
}

// ---------------------------------------------------------------------------
// S1: chunk transfer-matrix products, repack-free on 52-col padded X.
// Producers (warps 4-7): cp.async 8B chunks, row i of X (104B) -> smem row
// at 144B stride. Smem col-pads zeroed once. Consumers (warps 0-3):
// P <- max-rescale(P x X_t) with B via ldmatrix.trans (144B rows, conflict-free).
// K-row overruns (51..63) read finite neighbor data; nullified by P's zero pads.
// ---------------------------------------------------------------------------
#define TOFF(r, c) ((r) * 128 + ((((c) >> 3) ^ ((r) & 7)) << 4) + ((c) & 7) * 2)

__global__ __launch_bounds__(256) void s1_kernel(const float* __restrict__ mask) {
    const int c   = blockIdx.x;
    const int b   = blockIdx.y;
    const int tid = threadIdx.x;
    const int l   = tid & 31;
    const int wid = tid >> 5;

    const int t_first = (c == 0) ? 1 : c * CSZ;
    const int R = c * CSZ + CSZ - t_first;   // 15 (c==0) or 16

    __shared__ __align__(16) char raw[4 * SLOTB + 2048];  // ring + zero guard
    __shared__ __align__(16) __nv_bfloat16 P[64 * 64];
    __shared__ float sMax[4];
    __shared__ float s_m[CSZ];

    const char* XbB = (const char*)(g_X + (size_t)(b * TT) * ESTR);
    char* Pb = (char*)P;

    if (tid < R) s_m[tid] = mask[b * TT + t_first + tid];
    {
        uint4 z = {0, 0, 0, 0};
        for (int i = tid; i < 512; i += 256) ((uint4*)P)[i] = z;              // zero P
        for (int i = tid; i < 128; i += 256) *(uint4*)(raw + 4 * SLOTB + i * 16) = z; // guard
        // zero col-pads (bytes 104..143) of every row of all 4 slots, once
        if (tid < 204) {
            int slot = tid / 51, row = tid - slot * 51;
            char* rp = raw + slot * SLOTB + row * SROWB;
            uint2 z8 = {0, 0};
            *(uint2*)(rp + 104) = z8; *(uint2*)(rp + 112) = z8;
            *(uint2*)(rp + 120) = z8; *(uint2*)(rp + 128) = z8;
            *(uint2*)(rp + 136) = z8;
        }
    }

    // Producer prologue: issue rows 0..3 (clamped), rows 0..2 arrived after wait
    if (tid >= 128) {
        const int c0 = tid - 128;
        for (int r = 0; r < 4; r++) {
            int rr = (r < R) ? r : (R - 1);
            const char* src = XbB + (size_t)(t_first + rr) * (ESTR * 2);
            uint32_t dst = smem_u32(raw + r * SLOTB);
            for (int ch = c0; ch < XCH8; ch += 128) {
                int row = ch / 13, cc = ch - row * 13;
                cp_async8(dst + row * SROWB + cc * 8, src + row * 104 + cc * 8);
            }
            CP_COMMIT();
        }
        CP_WAIT(1);
    }
    __syncthreads();  // rows 0..2 + pad zeros + P zeros + s_m visible

    // P init = X_{t_first} (or identity if masked); pads stay zero
    if (tid < 128) {
        if (s_m[0] != 0.f) {
            const __nv_bfloat16* r0 = (const __nv_bfloat16*)raw;  // rows at 72-elem stride
            for (int e = tid; e < LBL * LBL; e += 128) {
                int i = e / LBL, j = e - i * LBL;
                *(__nv_bfloat16*)(Pb + TOFF(i, j)) = r0[i * 72 + j];
            }
        } else if (tid < LBL) {
            *(__nv_bfloat16*)(Pb + TOFF(tid, tid)) = __float2bfloat16(1.f);
        }
    }

    // Consumer fragment offsets
    const int mh = (wid >> 1) & 1, nh = wid & 1;
    const int a_r = l & 15, a_s = l >> 4;
    uint32_t a_off[2][4];
#pragma unroll
    for (int i = 0; i < 2; i++)
#pragma unroll
        for (int kk = 0; kk < 4; kk++) {
            int r = mh * 32 + 16 * i + a_r;
            int seg = 2 * kk + a_s;
            a_off[i][kk] = r * 128 + ((seg ^ (r & 7)) << 4);
        }
    // trans B: lane -> X row 16kk + 8*((l>>3)&1) + (l&7), col-byte (nh*32+16jj+8*(l>>4))*2
    const int bk  = 8 * ((l >> 3) & 1) + (l & 7);
    const int bnb = (nh * 32 + 8 * (l >> 4)) * 2;
    uint32_t bt_off[2][4];
#pragma unroll
    for (int jj = 0; jj < 2; jj++)
#pragma unroll
        for (int kk = 0; kk < 4; kk++)
            bt_off[jj][kk] = (uint32_t)((16 * kk + bk) * SROWB + bnb + 32 * jj);
    const uint32_t smP = smem_u32(P);
    const uint32_t smRaw0 = smem_u32(raw);

    float lsc = 0.f;

#pragma unroll 1
    for (int s = 1; s < R; s++) {
        __syncthreads();  // row s (+ overrun row s+1) + previous P visible

        if (tid >= 128) {
            int sf = s + 3; if (sf >= R) sf = R - 1;
            const char* src = XbB + (size_t)(t_first + sf) * (ESTR * 2);
            uint32_t dst = smem_u32(raw + ((s + 3) & 3) * SLOTB);
            const int c0 = tid - 128;
            for (int ch = c0; ch < XCH8; ch += 128) {
                int row = ch / 13, cc = ch - row * 13;
                cp_async8(dst + row * SROWB + cc * 8, src + row * 104 + cc * 8);
            }
            CP_COMMIT();
            CP_WAIT(1);  // rows <= s+2 arrived
        } else if (s_m[s] != 0.f) {
            const uint32_t smRaw = smRaw0 + (s & 3) * SLOTB;
            float cacc[2][4][4];
            float wmax = 0.f;
#pragma unroll
            for (int i = 0; i < 2; i++)
#pragma unroll
                for (int j = 0; j < 4; j++)
#pragma unroll
                    for (int q = 0; q < 4; q++) cacc[i][j][q] = 0.f;
#pragma unroll
            for (int kk = 0; kk < 4; kk++) {
                uint32_t a[2][4], bb[4][2];
#pragma unroll
                for (int i = 0; i < 2; i++)
                    LDSM4(a[i][0], a[i][1], a[i][2], a[i][3], smP + a_off[i][kk]);
#pragma unroll
                for (int jj = 0; jj < 2; jj++)
                    LDSM4_T(bb[2 * jj][0], bb[2 * jj][1], bb[2 * jj + 1][0], bb[2 * jj + 1][1],
                            smRaw + bt_off[jj][kk]);
#pragma unroll
                for (int i = 0; i < 2; i++)
#pragma unroll
                    for (int j = 0; j < 4; j++)
                        MMA16816(cacc[i][j], a[i], bb[j]);
            }
#pragma unroll
            for (int i = 0; i < 2; i++)
#pragma unroll
                for (int j = 0; j < 4; j++)
#pragma unroll
                    for (int q = 0; q < 4; q++) wmax = fmaxf(wmax, cacc[i][j][q]);
#pragma unroll
            for (int o = 16; o > 0; o >>= 1)
                wmax = fmaxf(wmax, __shfl_xor_sync(0xffffffffu, wmax, o));
            if (l == 0) sMax[wid] = wmax;
            asm volatile("bar.sync 1, 128;" ::: "memory");
            {
                float mx = fmaxf(fmaxf(sMax[0], sMax[1]), fmaxf(sMax[2], sMax[3]));
                float inv = __fdividef(1.f, mx);
                const int qr = l >> 2, qc = l & 3;
#pragma unroll
                for (int i = 0; i < 2; i++) {
                    int mr = mh * 32 + 16 * i + qr;
#pragma unroll
                    for (int j8 = 0; j8 < 4; j8++) {
                        int nc = nh * 32 + 8 * j8 + 2 * qc;
                        *(__nv_bfloat162*)(Pb + TOFF(mr, nc)) =
                            __floats2bfloat162_rn(cacc[i][j8][0] * inv, cacc[i][j8][1] * inv);
                        *(__nv_bfloat162*)(Pb + TOFF(mr + 8, nc)) =
                            __floats2bfloat162_rn(cacc[i][j8][2] * inv, cacc[i][j8][3] * inv);
                    }
                }
                if (tid == 0) lsc += __logf(mx);
            }
        }
    }
    __syncthreads();

    float* Mo = g_M + (size_t)(b * NCH + c) * MSTR;
    for (int e = tid; e < MSTR; e += 256) {
        int m = e >> 6, j = e & 63;
        Mo[e] = __bfloat162float(*(const __nv_bfloat16*)(Pb + TOFF(m, j)));
    }
    if (tid == 0) g_lsc[b * NCH + c] = lsc;
}

// ---------------------------------------------------------------------------
// S2: per-batch combine, 3-buffer lead-2 prefetch. X indices use 52-col rows.
// ---------------------------------------------------------------------------
__global__ __launch_bounds__(256) void s2_kernel(const int* __restrict__ target,
                                                 float* __restrict__ out) {
    const int b   = blockIdx.x;
    const int tid = threadIdx.x;
    const int l   = tid & 31;
    const int wid = tid >> 5;
    const int j   = tid & 63;
    const int g   = tid >> 6;

    __shared__ float v[64];
    __shared__ float red[256];
    __shared__ float wsum[8];
    __shared__ float sc[1];
    __shared__ float s_lsc[NCH];
    __shared__ int   s_tg[TT];
    __shared__ __align__(16) float Mb[3][MSTR];

    const __nv_bfloat16* Xb = g_X + (size_t)b * TT * ESTR;

    s_tg[tid] = target[b * TT + tid];
    if (tid < NCH) s_lsc[tid] = g_lsc[b * NCH + tid];

#pragma unroll
    for (int r = 0; r < 3; r++) {
        const char* src = (const char*)(g_M + (size_t)(b * NCH + r) * MSTR);
        uint32_t dst = smem_u32(Mb[r]);
        for (int ch = tid; ch < MSTR / 4; ch += 256) cp_async16(dst + ch * 16, src + ch * 16);
        CP_COMMIT();
    }
    __syncthreads();  // s_tg ready

    // target energy: X_t[prev, tg] at offset prev*52 + tg
    {
        int prev = (tid == 0) ? (LBL - 1) : s_tg[tid - 1];
        float e = __logf(__bfloat162float(Xb[(size_t)tid * ESTR + prev * 52 + s_tg[tid]]));
#pragma unroll
        for (int o = 16; o > 0; o >>= 1) e += __shfl_xor_sync(0xffffffffu, e, o);
        if (l == 0) wsum[wid] = e;
    }
    if (tid < 64)
        v[tid] = (tid < LBL) ? __bfloat162float(Xb[50 * 52 + tid]) : 0.f;  // t=0, row L-1

    float L = 0.f;

#pragma unroll 1
    for (int c = 0; c < NCH; c++) {
        CP_WAIT(2);
        __syncthreads();

        const float* M = Mb[c % 3];
        float sacc = 0.f;
#pragma unroll
        for (int it = 0; it < 13; it++) {
            int i = g + 4 * it;
            if (i < LBL) sacc += v[i] * M[i * 64 + j];
        }
        red[tid] = sacc;
        __syncthreads();

        if (c + 3 < NCH) {
            const char* src = (const char*)(g_M + (size_t)(b * NCH + c + 3) * MSTR);
            uint32_t dst = smem_u32(Mb[c % 3]);
            for (int ch = tid; ch < MSTR / 4; ch += 256) cp_async16(dst + ch * 16, src + ch * 16);
            CP_COMMIT();
        }

        if (g == 0) {
            float tot = red[j] + red[j + 64] + red[j + 128] + red[j + 192];
            red[j] = tot;
            if (j == 0) sc[0] = tot;
        }
        __syncthreads();
        if (g == 0) {
            float inv = __fdividef(1.f, sc[0]);
            v[j] = red[j] * inv;
            if (tid == 0) L += __logf(sc[0]) + s_lsc[c];
        }
    }
    __syncthreads();

    if (tid == 0) {
        float tg = 0.f;
#pragma unroll
        for (int w = 0; w < 8; w++) tg += wsum[w];
        float sm = 0.f;
        for (int jj = 0; jj < LBL; jj++) sm += v[jj];
        out[b] = L + __logf(sm) - tg;
    }
}

// ---------------------------------------------------------------------------
extern "C" void kernel_launch(void* const* d_in, const int* in_sizes, int n_in,
                              void* d_out, int out_size) {
    const float* input  = (const float*)d_in[0];
    const float* mask   = (const float*)d_in[1];
    const int*   target = (const int*)d_in[2];
    const float* sW     = (const float*)d_in[3];
    const float* sb     = (const float*)d_in[4];
    const float* tW     = (const float*)d_in[5];
    const float* tb     = (const float*)d_in[6];
    float* out = (float*)d_out;

    (void)in_sizes; (void)n_in; (void)out_size;

    prep_kernel<<<PREP_A_BLOCKS + PREP_W_BLOCKS, 256>>>(input, sW, sb, tW, tb);

    dim3 ggrid(NPAD / 128, MM / 128);  // (21, 128)
    gemm_exp_kernel<<<ggrid, 256>>>(mask);

    dim3 sgrid(NCH, BB);               // (16, 64)
    s1_kernel<<<sgrid, 256>>>(mask);

    s2_kernel<<<BB, 256>>>(target, out);
}